// round 3
// baseline (speedup 1.0000x reference)
#include <cuda_runtime.h>
#include <math.h>

#define BB 8
#define LL 8192
#define DD 768
#define NE 128
#define NPAIR (NE*(NE-1)/2)   // 8128
#define NP4   (DD/4)          // 192 float4 per row

#define NBLK  128
#define KSPLIT 16
#define KC     (DD/KSPLIT)    // 48
#define PITCH  132

typedef unsigned long long ull;

// Scratch (no allocations allowed)
__device__ float g_emb[BB*NE*DD];   // normalized embeddings
__device__ float g_sim[BB*NE*NE];   // cosine sims (atomic-accumulated, L2-only)
__device__ float g_cinv[BB];        // 1/(std+1e-5)
__device__ float g_mlp[4];          // collapsed MLP constants
__device__ int   g_flag;            // nonzero -> full-MLP fallback

// grid barrier state (generation compare is equality-based -> replay-safe)
__device__ volatile unsigned g_gen[4];
__device__ unsigned          g_cnt[4];

__device__ __forceinline__ void gbar(int i) {
    __syncthreads();
    if (threadIdx.x == 0) {
        const unsigned gen = g_gen[i];
        __threadfence();                       // order my writes before arrival
        const unsigned arr = atomicAdd(&g_cnt[i], 1u);
        if (arr == NBLK - 1) {
            g_cnt[i] = 0;
            __threadfence();
            g_gen[i] = gen + 1;                // release
        } else {
            while (g_gen[i] == gen) __nanosleep(64);
        }
    }
    __syncthreads();
}

// ---- packed f32x2 helpers ------------------------------------------------
__device__ __forceinline__ void fma2(ull &d, ull a, ull b) {
    asm("fma.rn.f32x2 %0, %1, %2, %0;" : "+l"(d) : "l"(a), "l"(b));
}
__device__ __forceinline__ ull pack2(float v) {
    ull r; unsigned u = __float_as_uint(v);
    asm("mov.b64 %0, {%1, %1};" : "=l"(r) : "r"(u));
    return r;
}
__device__ __forceinline__ void unpack2(ull v, float &lo, float &hi) {
    unsigned a, b;
    asm("mov.b64 {%0, %1}, %2;" : "=r"(a), "=r"(b) : "l"(v));
    lo = __uint_as_float(a); hi = __uint_as_float(b);
}

// ---------------------------------------------------------------------------
__global__ void __launch_bounds__(256, 1)
k_fused(const float* __restrict__ x,
        const int*   __restrict__ starts,
        const int*   __restrict__ lengths,
        const int*   __restrict__ hts,
        const float* __restrict__ thr,
        const float* __restrict__ W1,
        const float* __restrict__ b1,
        const float* __restrict__ W2,
        const float* __restrict__ b2,
        float*       __restrict__ out) {
    const int blk = blockIdx.x;          // 0..127
    const int tid = threadIdx.x;         // 256
    const int gtid = blk*256 + tid;      // 0..32767

    __shared__ __align__(16) float At[KC][PITCH];   // phase B tile
    __shared__ double rs[256], rq[256];             // phase C
    __shared__ float  wsum[6];
    __shared__ float  s_inv;

    // ---------------- Phase A: zero g_sim + span pool + normalize ----------
    __stcg(&((float4*)g_sim)[gtid], make_float4(0.f, 0.f, 0.f, 0.f));

    #pragma unroll 1
    for (int r = 0; r < 8; ++r) {
        const int sp  = blk*8 + r;                 // span id (b*NE + e)
        const int b   = sp >> 7;
        const int s   = starts[sp];
        const int len = lengths[sp];
        float4 e;
        float ss = 0.f;
        if (tid < 192) {
            const float inv_len = 1.0f / (float)len;
            const float4* base = (const float4*)x + ((long)b*LL + s)*NP4 + tid;
            float4 a0 = make_float4(0,0,0,0), a1 = a0, a2 = a0, a3 = a0;
            #pragma unroll
            for (int t = 0; t < 16; t += 4) {
                if (t   < len) { float4 v = base[(t  )*NP4]; a0.x+=v.x; a0.y+=v.y; a0.z+=v.z; a0.w+=v.w; }
                if (t+1 < len) { float4 v = base[(t+1)*NP4]; a1.x+=v.x; a1.y+=v.y; a1.z+=v.z; a1.w+=v.w; }
                if (t+2 < len) { float4 v = base[(t+2)*NP4]; a2.x+=v.x; a2.y+=v.y; a2.z+=v.z; a2.w+=v.w; }
                if (t+3 < len) { float4 v = base[(t+3)*NP4]; a3.x+=v.x; a3.y+=v.y; a3.z+=v.z; a3.w+=v.w; }
            }
            e.x = (a0.x+a1.x+a2.x+a3.x)*inv_len;
            e.y = (a0.y+a1.y+a2.y+a3.y)*inv_len;
            e.z = (a0.z+a1.z+a2.z+a3.z)*inv_len;
            e.w = (a0.w+a1.w+a2.w+a3.w)*inv_len;
            ss = e.x*e.x + e.y*e.y + e.z*e.z + e.w*e.w;
            #pragma unroll
            for (int o = 16; o > 0; o >>= 1) ss += __shfl_xor_sync(0xffffffffu, ss, o);
            if ((tid & 31) == 0) wsum[tid >> 5] = ss;
        }
        __syncthreads();
        if (tid == 0)
            s_inv = 1.0f / sqrtf(wsum[0]+wsum[1]+wsum[2]+wsum[3]+wsum[4]+wsum[5]);
        __syncthreads();
        if (tid < 192) {
            const float inv = s_inv;
            ((float4*)g_emb)[(long)sp*NP4 + tid] =
                make_float4(e.x*inv, e.y*inv, e.z*inv, e.w*inv);
        }
    }

    gbar(0);

    // ---------------- Phase B: split-K syrk (cosine gram) ------------------
    {
        const int b  = blk >> 4;
        const int kc = blk & 15;
        const int ty = tid >> 4, tx = tid & 15;
        const int i8 = ty*8, j8 = tx*8;

        const float4* Eb4 = (const float4*)g_emb + (long)b*NE*NP4 + kc*(KC/4);
        #pragma unroll
        for (int e = 0; e < 6; ++e) {
            const int idx = tid + e*256;
            const int j  = idx & 127;
            const int kg = idx >> 7;
            float4 v = Eb4[(long)j*NP4 + kg];
            At[4*kg+0][j] = v.x;
            At[4*kg+1][j] = v.y;
            At[4*kg+2][j] = v.z;
            At[4*kg+3][j] = v.w;
        }
        __syncthreads();

        ull c[8][4];
        #pragma unroll
        for (int r = 0; r < 8; ++r)
            #pragma unroll
            for (int q = 0; q < 4; ++q) c[r][q] = 0ull;

        #pragma unroll 4
        for (int kk = 0; kk < KC; ++kk) {
            ull a2[8];
            #pragma unroll
            for (int r = 0; r < 8; ++r) a2[r] = pack2(At[kk][i8 + r]);
            const ulonglong2 b0 = *(const ulonglong2*)&At[kk][j8];
            const ulonglong2 b1 = *(const ulonglong2*)&At[kk][j8 + 4];
            ull bb[4] = {b0.x, b0.y, b1.x, b1.y};
            #pragma unroll
            for (int r = 0; r < 8; ++r)
                #pragma unroll
                for (int q = 0; q < 4; ++q) fma2(c[r][q], a2[r], bb[q]);
        }

        float* S = g_sim + ((long)b*NE + i8)*NE + j8;
        #pragma unroll
        for (int r = 0; r < 8; ++r)
            #pragma unroll
            for (int q = 0; q < 4; ++q) {
                float lo, hi;
                unpack2(c[r][q], lo, hi);
                atomicAdd(&S[(long)r*NE + 2*q    ], lo);
                atomicAdd(&S[(long)r*NE + 2*q + 1], hi);
            }
    }

    gbar(1);

    // ---------------- Phase C: stats + MLP collapse -------------------------
    if (blk < BB) {
        const float4* S4 = (const float4*)(g_sim + (long)blk*NE*NE);
        double s = 0.0, q = 0.0;
        #pragma unroll
        for (int it = 0; it < 16; ++it) {
            const float4 v = __ldcg(&S4[tid + it*256]);
            s += (double)v.x + (double)v.y + (double)v.z + (double)v.w;
            q += (double)v.x*v.x + (double)v.y*v.y
               + (double)v.z*v.z + (double)v.w*v.w;
        }
        rs[tid] = s; rq[tid] = q;
        __syncthreads();
        #pragma unroll
        for (int o = 128; o > 0; o >>= 1) {
            if (tid < o) { rs[tid] += rs[tid+o]; rq[tid] += rq[tid+o]; }
            __syncthreads();
        }
        if (tid == 0) {
            const double n  = (double)(NE*NE);
            const double sd = sqrt((rq[0] - rs[0]*rs[0]/n) / (n - 1.0));
            g_cinv[blk] = 1.0f / ((float)sd + 1e-5f);
        }
    } else if (blk == BB) {
        __shared__ float r0[128], r1[128], r2[128], r3[128];
        __shared__ int   rf[128];
        if (tid < 128) {
            const float w1  = W1[tid];
            const float w20 = W2[2*tid], w21 = W2[2*tid+1];
            r0[tid] = (w1 > 0.f) ? w1*w20 : 0.f;
            r1[tid] = (w1 > 0.f) ? w1*w21 : 0.f;
            r2[tid] = (w1 < 0.f) ? w1*w20 : 0.f;
            r3[tid] = (w1 < 0.f) ? w1*w21 : 0.f;
            rf[tid] = (b1[tid] != 0.f) ? 1 : 0;
        }
        __syncthreads();
        #pragma unroll
        for (int o = 64; o > 0; o >>= 1) {
            if (tid < o) {
                r0[tid]+=r0[tid+o]; r1[tid]+=r1[tid+o];
                r2[tid]+=r2[tid+o]; r3[tid]+=r3[tid+o];
                rf[tid]|=rf[tid+o];
            }
            __syncthreads();
        }
        if (tid == 0) {
            g_mlp[0]=r0[0]; g_mlp[1]=r1[0]; g_mlp[2]=r2[0]; g_mlp[3]=r3[0];
            g_flag = rf[0];
        }
    }

    gbar(2);

    // ---------------- Phase D: gather pairs + classify ----------------------
    {
        const float t0  = __ldg(thr);
        const float b20 = __ldg(&b2[0]), b21 = __ldg(&b2[1]);
        const int   flg = __ldcg(&g_flag);
        const float m0p = __ldcg(&g_mlp[0]), m1p = __ldcg(&g_mlp[1]);
        const float m0n = __ldcg(&g_mlp[2]), m1n = __ldcg(&g_mlp[3]);

        #pragma unroll
        for (int it = 0; it < 2; ++it) {
            const int gp = gtid + it*32768;
            if (gp < BB*NPAIR) {
                const int b = gp / NPAIR;
                const int2 ht = ((const int2*)hts)[gp];
                const float sim = __ldcg(&g_sim[((long)b*NE + ht.x)*NE + ht.y]);
                const float pv  = (sim - t0) * __ldcg(&g_cinv[b]);
                float o0, o1;
                if (flg == 0) {
                    o0 = fmaf(pv, (pv > 0.f) ? m0p : m0n, b20);
                    o1 = fmaf(pv, (pv > 0.f) ? m1p : m1n, b21);
                } else {
                    o0 = b20; o1 = b21;
                    #pragma unroll 8
                    for (int k = 0; k < 128; ++k) {
                        const float h = fmaxf(fmaf(pv, __ldg(&W1[k]), __ldg(&b1[k])), 0.f);
                        o0 = fmaf(h, __ldg(&W2[2*k  ]), o0);
                        o1 = fmaf(h, __ldg(&W2[2*k+1]), o1);
                    }
                }
                ((float2*)out)[gp] = make_float2(o0, o1);
            }
        }
    }
}

// ---------------------------------------------------------------------------
extern "C" void kernel_launch(void* const* d_in, const int* in_sizes, int n_in,
                              void* d_out, int out_size) {
    const float* x       = (const float*)d_in[0];
    const int*   starts  = (const int*)  d_in[1];
    const int*   lengths = (const int*)  d_in[2];
    const int*   hts     = (const int*)  d_in[3];
    const float* thr     = (const float*)d_in[4];
    const float* W1      = (const float*)d_in[5];
    const float* b1      = (const float*)d_in[6];
    const float* W2      = (const float*)d_in[7];
    const float* b2      = (const float*)d_in[8];
    float* out = (float*)d_out;

    k_fused<<<NBLK, 256>>>(x, starts, lengths, hts, thr, W1, b1, W2, b2, out);
}

// round 4
// speedup vs baseline: 1.2943x; 1.2943x over previous
#include <cuda_runtime.h>
#include <math.h>

#define BB 8
#define LL 8192
#define DD 768
#define NE 128
#define NPAIR (NE*(NE-1)/2)   // 8128
#define NP4   (DD/4)          // 192 float4 per row

#define NBLK   256
#define KSPLIT 16
#define KC     (DD/KSPLIT)    // 48
#define PITCH  132

typedef unsigned long long ull;

// Scratch (no allocations allowed)
__device__ float  g_emb[BB*NE*DD];   // normalized embeddings
__device__ float  g_sim[BB*NE*NE];   // cosine sims (atomic-accumulated, L2)
__device__ double g_stats[2*BB];     // per-batch {sum, sumsq}
__device__ float  g_mlp[4];          // collapsed MLP constants
__device__ int    g_flag;            // nonzero -> full-MLP fallback

// grid barrier (generation equality-compare -> replay-safe)
__device__ volatile unsigned g_gen[4];
__device__ unsigned          g_cnt[4];

__device__ __forceinline__ void gbar(int i) {
    __syncthreads();
    if (threadIdx.x == 0) {
        const unsigned gen = g_gen[i];
        __threadfence();
        const unsigned arr = atomicAdd(&g_cnt[i], 1u);
        if (arr == NBLK - 1) {
            g_cnt[i] = 0;
            __threadfence();
            g_gen[i] = gen + 1;
        } else {
            while (g_gen[i] == gen) __nanosleep(32);
        }
    }
    __syncthreads();
}

// ---- packed f32x2 helpers ------------------------------------------------
__device__ __forceinline__ void fma2(ull &d, ull a, ull b) {
    asm("fma.rn.f32x2 %0, %1, %2, %0;" : "+l"(d) : "l"(a), "l"(b));
}
__device__ __forceinline__ ull pack2(float v) {
    ull r; unsigned u = __float_as_uint(v);
    asm("mov.b64 %0, {%1, %1};" : "=l"(r) : "r"(u));
    return r;
}
__device__ __forceinline__ void unpack2(ull v, float &lo, float &hi) {
    unsigned a, b;
    asm("mov.b64 {%0, %1}, %2;" : "=r"(a), "=r"(b) : "l"(v));
    lo = __uint_as_float(a); hi = __uint_as_float(b);
}

// ---------------------------------------------------------------------------
__global__ void __launch_bounds__(256, 2)
k_fused(const float* __restrict__ x,
        const int*   __restrict__ starts,
        const int*   __restrict__ lengths,
        const int*   __restrict__ hts,
        const float* __restrict__ thr,
        const float* __restrict__ W1,
        const float* __restrict__ b1,
        const float* __restrict__ W2,
        const float* __restrict__ b2,
        float*       __restrict__ out) {
    const int blk  = blockIdx.x;          // 0..255
    const int tid  = threadIdx.x;         // 256
    const int gtid = blk*256 + tid;       // 0..65535
    const int wid  = tid >> 5;            // 0..7
    const int lane = tid & 31;

    __shared__ __align__(16) float At[KC][PITCH];   // phase B (25.3 KB)
    __shared__ float sA[8];                          // phase A norm exchange
    __shared__ double sS[8], sQ[8];                  // phase C warp partials
    __shared__ float r0[128], r1[128], r2[128], r3[128];
    __shared__ int   rf[128];

    // ================= Phase A: zero scratch + span pool (1 span / warp) ===
    if (gtid < (BB*NE*NE)/4)
        __stcg(&((float4*)g_sim)[gtid], make_float4(0.f, 0.f, 0.f, 0.f));
    if (blk == 0 && tid < 2*BB) g_stats[tid] = 0.0;

    {
        const int gw   = blk*8 + wid;     // 0..2047
        const int sp   = gw >> 1;         // span id = b*NE + e
        const int half = gw & 1;          // which half of D
        const int b    = sp >> 7;
        const int s    = starts[sp];
        const int len  = lengths[sp];
        const float inv_len = 1.0f / (float)len;
        const int d0 = half*96 + lane;    // f4 index
        const float4* base = (const float4*)x + ((long)b*LL + s)*NP4 + d0;

        float4 e0 = make_float4(0,0,0,0), e1 = e0, e2 = e0;
        #pragma unroll
        for (int t = 0; t < 16; ++t) {
            if (t < len) {
                float4 v0 = base[(long)t*NP4     ];
                float4 v1 = base[(long)t*NP4 + 32];
                float4 v2 = base[(long)t*NP4 + 64];
                e0.x+=v0.x; e0.y+=v0.y; e0.z+=v0.z; e0.w+=v0.w;
                e1.x+=v1.x; e1.y+=v1.y; e1.z+=v1.z; e1.w+=v1.w;
                e2.x+=v2.x; e2.y+=v2.y; e2.z+=v2.z; e2.w+=v2.w;
            }
        }
        e0.x*=inv_len; e0.y*=inv_len; e0.z*=inv_len; e0.w*=inv_len;
        e1.x*=inv_len; e1.y*=inv_len; e1.z*=inv_len; e1.w*=inv_len;
        e2.x*=inv_len; e2.y*=inv_len; e2.z*=inv_len; e2.w*=inv_len;

        float ss = e0.x*e0.x + e0.y*e0.y + e0.z*e0.z + e0.w*e0.w
                 + e1.x*e1.x + e1.y*e1.y + e1.z*e1.z + e1.w*e1.w
                 + e2.x*e2.x + e2.y*e2.y + e2.z*e2.z + e2.w*e2.w;
        #pragma unroll
        for (int o = 16; o > 0; o >>= 1) ss += __shfl_xor_sync(0xffffffffu, ss, o);
        if (lane == 0) sA[wid] = ss;
        __syncthreads();
        const float inv = 1.0f / sqrtf(sA[wid & ~1] + sA[wid | 1]);
        float4* Eo = (float4*)g_emb + (long)sp*NP4 + d0;
        __stcg(&Eo[ 0], make_float4(e0.x*inv, e0.y*inv, e0.z*inv, e0.w*inv));
        __stcg(&Eo[32], make_float4(e1.x*inv, e1.y*inv, e1.z*inv, e1.w*inv));
        __stcg(&Eo[64], make_float4(e2.x*inv, e2.y*inv, e2.z*inv, e2.w*inv));
    }

    gbar(0);

    // ================= Phase B: split-K syrk on blocks 0..127 ==============
    if (blk < 128) {
        const int b  = blk >> 4;
        const int kc = blk & 15;
        const int ty = tid >> 4, tx = tid & 15;
        const int i8 = ty*8, j8 = tx*8;

        const float4* Eb4 = (const float4*)g_emb + (long)b*NE*NP4 + kc*(KC/4);
        #pragma unroll
        for (int e = 0; e < 6; ++e) {
            const int idx = tid + e*256;
            const int j  = idx & 127;
            const int kg = idx >> 7;
            float4 v = __ldcg(&Eb4[(long)j*NP4 + kg]);
            At[4*kg+0][j] = v.x;
            At[4*kg+1][j] = v.y;
            At[4*kg+2][j] = v.z;
            At[4*kg+3][j] = v.w;
        }
        __syncthreads();

        ull c[8][4];
        #pragma unroll
        for (int r = 0; r < 8; ++r)
            #pragma unroll
            for (int q = 0; q < 4; ++q) c[r][q] = 0ull;

        #pragma unroll 4
        for (int kk = 0; kk < KC; ++kk) {
            ull a2[8];
            #pragma unroll
            for (int r = 0; r < 8; ++r) a2[r] = pack2(At[kk][i8 + r]);
            const ulonglong2 bv0 = *(const ulonglong2*)&At[kk][j8];
            const ulonglong2 bv1 = *(const ulonglong2*)&At[kk][j8 + 4];
            ull bb[4] = {bv0.x, bv0.y, bv1.x, bv1.y};
            #pragma unroll
            for (int r = 0; r < 8; ++r)
                #pragma unroll
                for (int q = 0; q < 4; ++q) fma2(c[r][q], a2[r], bb[q]);
        }

        float* S = g_sim + ((long)b*NE + i8)*NE + j8;
        #pragma unroll
        for (int r = 0; r < 8; ++r)
            #pragma unroll
            for (int q = 0; q < 4; ++q) {
                float lo, hi;
                unpack2(c[r][q], lo, hi);
                atomicAdd(&S[(long)r*NE + 2*q    ], lo);
                atomicAdd(&S[(long)r*NE + 2*q + 1], hi);
            }
    }

    gbar(1);

    // ================= Phase C: stats (32 blocks) + MLP collapse ===========
    if (blk < 32) {
        const int b = blk >> 2;           // batch
        const int q = blk & 3;            // quarter
        const float4* S4 = (const float4*)(g_sim + (long)b*NE*NE) + q*1024;
        double s = 0.0, qq = 0.0;
        #pragma unroll
        for (int it = 0; it < 4; ++it) {
            const float4 v = __ldcg(&S4[tid + it*256]);
            s  += (double)v.x + (double)v.y + (double)v.z + (double)v.w;
            qq += (double)v.x*v.x + (double)v.y*v.y
                + (double)v.z*v.z + (double)v.w*v.w;
        }
        #pragma unroll
        for (int o = 16; o > 0; o >>= 1) {
            s  += __shfl_xor_sync(0xffffffffu, s,  o);
            qq += __shfl_xor_sync(0xffffffffu, qq, o);
        }
        if (lane == 0) { sS[wid] = s; sQ[wid] = qq; }
        __syncthreads();
        if (tid == 0) {
            double ts = 0.0, tq = 0.0;
            #pragma unroll
            for (int w = 0; w < 8; ++w) { ts += sS[w]; tq += sQ[w]; }
            atomicAdd(&g_stats[b*2    ], ts);
            atomicAdd(&g_stats[b*2 + 1], tq);
        }
    } else if (blk == 32) {
        if (tid < 128) {
            const float w1  = W1[tid];
            const float w20 = W2[2*tid], w21 = W2[2*tid+1];
            r0[tid] = (w1 > 0.f) ? w1*w20 : 0.f;
            r1[tid] = (w1 > 0.f) ? w1*w21 : 0.f;
            r2[tid] = (w1 < 0.f) ? w1*w20 : 0.f;
            r3[tid] = (w1 < 0.f) ? w1*w21 : 0.f;
            rf[tid] = (b1[tid] != 0.f) ? 1 : 0;
        }
        __syncthreads();
        #pragma unroll
        for (int o = 64; o > 0; o >>= 1) {
            if (tid < o) {
                r0[tid]+=r0[tid+o]; r1[tid]+=r1[tid+o];
                r2[tid]+=r2[tid+o]; r3[tid]+=r3[tid+o];
                rf[tid]|=rf[tid+o];
            }
            __syncthreads();
        }
        if (tid == 0) {
            g_mlp[0]=r0[0]; g_mlp[1]=r1[0]; g_mlp[2]=r2[0]; g_mlp[3]=r3[0];
            g_flag = rf[0];
        }
    }

    gbar(2);

    // ================= Phase D: gather + std + classify (1 pair/thread) ====
    if (gtid < BB*NPAIR) {
        const float t0  = __ldg(thr);
        const float b20 = __ldg(&b2[0]), b21 = __ldg(&b2[1]);
        const int   flg = __ldcg(&g_flag);

        const int b = gtid / NPAIR;
        const double sum = __ldcg(&g_stats[b*2]);
        const double sq  = __ldcg(&g_stats[b*2 + 1]);
        const double n   = (double)(NE*NE);
        const float  sd  = (float)sqrt((sq - sum*sum/n) / (n - 1.0));
        const float  cinv = 1.0f / (sd + 1e-5f);

        const int2 ht = ((const int2*)hts)[gtid];
        const float sim = __ldcg(&g_sim[((long)b*NE + ht.x)*NE + ht.y]);
        const float pv  = (sim - t0) * cinv;

        float o0, o1;
        if (flg == 0) {
            const float m0 = (pv > 0.f) ? __ldcg(&g_mlp[0]) : __ldcg(&g_mlp[2]);
            const float m1 = (pv > 0.f) ? __ldcg(&g_mlp[1]) : __ldcg(&g_mlp[3]);
            o0 = fmaf(pv, m0, b20);
            o1 = fmaf(pv, m1, b21);
        } else {
            o0 = b20; o1 = b21;
            #pragma unroll 8
            for (int k = 0; k < 128; ++k) {
                const float h = fmaxf(fmaf(pv, __ldg(&W1[k]), __ldg(&b1[k])), 0.f);
                o0 = fmaf(h, __ldg(&W2[2*k  ]), o0);
                o1 = fmaf(h, __ldg(&W2[2*k+1]), o1);
            }
        }
        ((float2*)out)[gtid] = make_float2(o0, o1);
    }
}

// ---------------------------------------------------------------------------
extern "C" void kernel_launch(void* const* d_in, const int* in_sizes, int n_in,
                              void* d_out, int out_size) {
    const float* x       = (const float*)d_in[0];
    const int*   starts  = (const int*)  d_in[1];
    const int*   lengths = (const int*)  d_in[2];
    const int*   hts     = (const int*)  d_in[3];
    const float* thr     = (const float*)d_in[4];
    const float* W1      = (const float*)d_in[5];
    const float* b1      = (const float*)d_in[6];
    const float* W2      = (const float*)d_in[7];
    const float* b2      = (const float*)d_in[8];
    float* out = (float*)d_out;

    k_fused<<<NBLK, 256>>>(x, starts, lengths, hts, thr, W1, b1, W2, b2, out);
}

// round 5
// speedup vs baseline: 1.5861x; 1.2254x over previous
#include <cuda_runtime.h>
#include <math.h>

#define BB 8
#define LL 8192
#define DD 768
#define NE 128
#define NPAIR (NE*(NE-1)/2)   // 8128
#define NP4   (DD/4)          // 192 float4 per row

#define KSPLIT 16
#define KC     (DD/KSPLIT)    // 48
#define PITCH  132

typedef unsigned long long ull;

// Scratch (no allocations allowed)
__device__ float  g_emb[BB*NE*DD];   // normalized embeddings
__device__ float  g_sim[BB*NE*NE];   // cosine sims (atomic-accumulated)
__device__ double g_stats[2*BB];     // per-batch {sum, sumsq}
__device__ float  g_cinv[BB];        // 1/(std+1e-5)  (finalized ONCE per batch)
__device__ float  g_mlp[4];          // collapsed MLP constants
__device__ int    g_flag;            // nonzero -> full-MLP fallback

// ---- packed f32x2 helpers ------------------------------------------------
__device__ __forceinline__ void fma2(ull &d, ull a, ull b) {
    asm("fma.rn.f32x2 %0, %1, %2, %0;" : "+l"(d) : "l"(a), "l"(b));
}
__device__ __forceinline__ ull pack2(float v) {
    ull r; unsigned u = __float_as_uint(v);
    asm("mov.b64 %0, {%1, %1};" : "=l"(r) : "r"(u));
    return r;
}
__device__ __forceinline__ void unpack2(ull v, float &lo, float &hi) {
    unsigned a, b;
    asm("mov.b64 {%0, %1}, %2;" : "=r"(a), "=r"(b) : "l"(v));
    lo = __uint_as_float(a); hi = __uint_as_float(b);
}

// ---------------------------------------------------------------------------
// K1: span mean pool -> normalized embedding. One block (192 thr) per (b,e).
//     Also zeroes g_sim and g_stats.
// ---------------------------------------------------------------------------
__global__ void __launch_bounds__(192)
k_pool(const float* __restrict__ x,
       const int*   __restrict__ starts,
       const int*   __restrict__ lengths) {
    const int blk = blockIdx.x;          // b*NE + e
    const int tid = threadIdx.x;         // 192
    const int b   = blk >> 7;

    if (tid < 32)                        // zero sim accumulator (32 f4 each)
        __stcg(&((float4*)g_sim)[blk*32 + tid], make_float4(0.f,0.f,0.f,0.f));
    if (blk == 0 && tid < 2*BB) g_stats[tid] = 0.0;

    const int s   = starts[blk];
    const int len = lengths[blk];
    const float inv_len = 1.0f / (float)len;
    const float4* base = (const float4*)x + ((long)b*LL + s)*NP4 + tid;

    float4 a0 = make_float4(0,0,0,0), a1 = a0, a2 = a0, a3 = a0;
    #pragma unroll
    for (int t = 0; t < 16; t += 4) {
        if (t   < len) { float4 v = base[(t  )*NP4]; a0.x+=v.x; a0.y+=v.y; a0.z+=v.z; a0.w+=v.w; }
        if (t+1 < len) { float4 v = base[(t+1)*NP4]; a1.x+=v.x; a1.y+=v.y; a1.z+=v.z; a1.w+=v.w; }
        if (t+2 < len) { float4 v = base[(t+2)*NP4]; a2.x+=v.x; a2.y+=v.y; a2.z+=v.z; a2.w+=v.w; }
        if (t+3 < len) { float4 v = base[(t+3)*NP4]; a3.x+=v.x; a3.y+=v.y; a3.z+=v.z; a3.w+=v.w; }
    }
    float4 e;
    e.x = (a0.x+a1.x+a2.x+a3.x)*inv_len;
    e.y = (a0.y+a1.y+a2.y+a3.y)*inv_len;
    e.z = (a0.z+a1.z+a2.z+a3.z)*inv_len;
    e.w = (a0.w+a1.w+a2.w+a3.w)*inv_len;

    float ss = e.x*e.x + e.y*e.y + e.z*e.z + e.w*e.w;
    #pragma unroll
    for (int o = 16; o > 0; o >>= 1) ss += __shfl_xor_sync(0xffffffffu, ss, o);

    __shared__ float wsum[6];
    __shared__ float s_inv;
    if ((tid & 31) == 0) wsum[tid >> 5] = ss;
    __syncthreads();
    if (tid == 0)
        s_inv = 1.0f / sqrtf(wsum[0]+wsum[1]+wsum[2]+wsum[3]+wsum[4]+wsum[5]);
    __syncthreads();
    const float inv = s_inv;
    ((float4*)g_emb)[(long)blk*NP4 + tid] =
        make_float4(e.x*inv, e.y*inv, e.z*inv, e.w*inv);
}

// ---------------------------------------------------------------------------
// K2: split-K syrk. grid (KSPLIT, BB), 256 threads, up to 255 regs (no cap).
//     8x8 per-thread tiles, packed FFMA2, atomicAdd partials into g_sim.
// ---------------------------------------------------------------------------
__global__ void __launch_bounds__(256, 1) k_sim(void) {
    const int b  = blockIdx.y;
    const int kc = blockIdx.x;
    const int tid = threadIdx.x;
    const int ty = tid >> 4;             // 0..15
    const int tx = tid & 15;             // 0..15
    const int i8 = ty*8, j8 = tx*8;

    __shared__ __align__(16) float At[KC][PITCH];   // [k][i], transposed

    const float4* Eb4 = (const float4*)g_emb + (long)b*NE*NP4 + kc*(KC/4);
    #pragma unroll
    for (int e = 0; e < 6; ++e) {
        const int idx = tid + e*256;     // 0..1535
        const int j  = idx & 127;
        const int kg = idx >> 7;         // 0..11
        float4 v = Eb4[(long)j*NP4 + kg];
        At[4*kg+0][j] = v.x;
        At[4*kg+1][j] = v.y;
        At[4*kg+2][j] = v.z;
        At[4*kg+3][j] = v.w;
    }
    __syncthreads();

    ull c[8][4];
    #pragma unroll
    for (int r = 0; r < 8; ++r)
        #pragma unroll
        for (int q = 0; q < 4; ++q) c[r][q] = 0ull;

    #pragma unroll 4
    for (int kk = 0; kk < KC; ++kk) {
        const float4 alo = *(const float4*)&At[kk][i8];
        const float4 ahi = *(const float4*)&At[kk][i8 + 4];
        ull a2[8];
        a2[0]=pack2(alo.x); a2[1]=pack2(alo.y); a2[2]=pack2(alo.z); a2[3]=pack2(alo.w);
        a2[4]=pack2(ahi.x); a2[5]=pack2(ahi.y); a2[6]=pack2(ahi.z); a2[7]=pack2(ahi.w);
        const ulonglong2 bv0 = *(const ulonglong2*)&At[kk][j8];
        const ulonglong2 bv1 = *(const ulonglong2*)&At[kk][j8 + 4];
        ull bb[4] = {bv0.x, bv0.y, bv1.x, bv1.y};
        #pragma unroll
        for (int r = 0; r < 8; ++r)
            #pragma unroll
            for (int q = 0; q < 4; ++q) fma2(c[r][q], a2[r], bb[q]);
    }

    float* S = g_sim + ((long)b*NE + i8)*NE + j8;
    #pragma unroll
    for (int r = 0; r < 8; ++r)
        #pragma unroll
        for (int q = 0; q < 4; ++q) {
            float lo, hi;
            unpack2(c[r][q], lo, hi);
            atomicAdd(&S[(long)r*NE + 2*q    ], lo);
            atomicAdd(&S[(long)r*NE + 2*q + 1], hi);
        }
}

// ---------------------------------------------------------------------------
// K3: blocks 0..31: per-batch fp64 stats partials (4 blocks/batch).
//     block 32: collapse MLP.  Finalization of cinv happens in block 33 after
//     a device-wide dependency?  No -- partials need all 4 blocks; instead
//     each of the 4 blocks atomically accumulates, and the LAST arriver for
//     its batch finalizes cinv (ticket via atomicAdd counter, replay-safe:
//     counter returns to 0 every launch).
// ---------------------------------------------------------------------------
__device__ unsigned g_done[BB];   // arrival counters (reset by finalizer)

__global__ void __launch_bounds__(256)
k_stats(const float* __restrict__ W1,
        const float* __restrict__ b1,
        const float* __restrict__ W2) {
    const int blk = blockIdx.x;
    const int tid = threadIdx.x;         // 256
    const int lane = tid & 31;
    const int wid  = tid >> 5;

    if (blk < 32) {
        const int b = blk >> 2;
        const int q = blk & 3;
        const float4* S4 = (const float4*)(g_sim + (long)b*NE*NE) + q*1024;
        double s = 0.0, qq = 0.0;
        #pragma unroll
        for (int it = 0; it < 4; ++it) {
            const float4 v = S4[tid + it*256];
            s  += (double)v.x + (double)v.y + (double)v.z + (double)v.w;
            qq += (double)v.x*v.x + (double)v.y*v.y
                + (double)v.z*v.z + (double)v.w*v.w;
        }
        #pragma unroll
        for (int o = 16; o > 0; o >>= 1) {
            s  += __shfl_xor_sync(0xffffffffu, s,  o);
            qq += __shfl_xor_sync(0xffffffffu, qq, o);
        }
        __shared__ double sS[8], sQ[8];
        if (lane == 0) { sS[wid] = s; sQ[wid] = qq; }
        __syncthreads();
        if (tid == 0) {
            double ts = 0.0, tq = 0.0;
            #pragma unroll
            for (int w = 0; w < 8; ++w) { ts += sS[w]; tq += sQ[w]; }
            atomicAdd(&g_stats[b*2    ], ts);
            atomicAdd(&g_stats[b*2 + 1], tq);
            __threadfence();
            const unsigned arr = atomicAdd(&g_done[b], 1u);
            if (arr == 3u) {             // last arriver finalizes (once)
                g_done[b] = 0u;          // reset for next replay
                const double sum = g_stats[b*2];
                const double sq  = g_stats[b*2 + 1];
                const double n   = (double)(NE*NE);
                const double sd  = sqrt((sq - sum*sum/n) / (n - 1.0));
                g_cinv[b] = 1.0f / ((float)sd + 1e-5f);
            }
        }
    } else {
        __shared__ float r0[128], r1[128], r2[128], r3[128];
        __shared__ int   rf[128];
        if (tid < 128) {
            const float w1  = W1[tid];
            const float w20 = W2[2*tid], w21 = W2[2*tid+1];
            r0[tid] = (w1 > 0.f) ? w1*w20 : 0.f;
            r1[tid] = (w1 > 0.f) ? w1*w21 : 0.f;
            r2[tid] = (w1 < 0.f) ? w1*w20 : 0.f;
            r3[tid] = (w1 < 0.f) ? w1*w21 : 0.f;
            rf[tid] = (b1[tid] != 0.f) ? 1 : 0;
        }
        __syncthreads();
        #pragma unroll
        for (int o = 64; o > 0; o >>= 1) {
            if (tid < o) {
                r0[tid]+=r0[tid+o]; r1[tid]+=r1[tid+o];
                r2[tid]+=r2[tid+o]; r3[tid]+=r3[tid+o];
                rf[tid]|=rf[tid+o];
            }
            __syncthreads();
        }
        if (tid == 0) {
            g_mlp[0]=r0[0]; g_mlp[1]=r1[0]; g_mlp[2]=r2[0]; g_mlp[3]=r3[0];
            g_flag = rf[0];
        }
    }
}

// ---------------------------------------------------------------------------
// K4: gather pairs, standardize with precomputed float cinv, classify.
//     NO fp64 anywhere.
// ---------------------------------------------------------------------------
__global__ void __launch_bounds__(256)
k_cls(const int*   __restrict__ hts,
      const float* __restrict__ thr,
      const float* __restrict__ W1,
      const float* __restrict__ b1,
      const float* __restrict__ W2,
      const float* __restrict__ b2,
      float*       __restrict__ out) {
    const int gp = blockIdx.x * 256 + threadIdx.x;
    if (gp >= BB * NPAIR) return;

    const int b = gp / NPAIR;            // const divisor -> mul/shift
    const int2 ht = ((const int2*)hts)[gp];
    const float sim = g_sim[((long)b*NE + ht.x)*NE + ht.y];
    const float pv  = (sim - __ldg(thr)) * g_cinv[b];
    const float b20 = __ldg(&b2[0]), b21 = __ldg(&b2[1]);

    float o0, o1;
    if (g_flag == 0) {
        const float m0 = (pv > 0.f) ? g_mlp[0] : g_mlp[2];
        const float m1 = (pv > 0.f) ? g_mlp[1] : g_mlp[3];
        o0 = fmaf(pv, m0, b20);
        o1 = fmaf(pv, m1, b21);
    } else {
        o0 = b20; o1 = b21;
        #pragma unroll 8
        for (int k = 0; k < 128; ++k) {
            const float h = fmaxf(fmaf(pv, __ldg(&W1[k]), __ldg(&b1[k])), 0.f);
            o0 = fmaf(h, __ldg(&W2[2*k  ]), o0);
            o1 = fmaf(h, __ldg(&W2[2*k+1]), o1);
        }
    }
    ((float2*)out)[gp] = make_float2(o0, o1);
}

// ---------------------------------------------------------------------------
extern "C" void kernel_launch(void* const* d_in, const int* in_sizes, int n_in,
                              void* d_out, int out_size) {
    const float* x       = (const float*)d_in[0];
    const int*   starts  = (const int*)  d_in[1];
    const int*   lengths = (const int*)  d_in[2];
    const int*   hts     = (const int*)  d_in[3];
    const float* thr     = (const float*)d_in[4];
    const float* W1      = (const float*)d_in[5];
    const float* b1      = (const float*)d_in[6];
    const float* W2      = (const float*)d_in[7];
    const float* b2      = (const float*)d_in[8];
    float* out = (float*)d_out;

    k_pool<<<BB*NE, 192>>>(x, starts, lengths);
    dim3 gsim(KSPLIT, BB);
    k_sim<<<gsim, 256>>>();
    k_stats<<<33, 256>>>(W1, b1, W2);
    k_cls<<<(BB*NPAIR + 255)/256, 256>>>(hts, thr, W1, b1, W2, b2, out);
}